// round 1
// baseline (speedup 1.0000x reference)
#include <cuda_runtime.h>

#define Nn   20000
#define Ee   640000
#define ETOT (Ee + Nn)
#define Bb   16
#define HC   256
#define EPSn 1e-5f

// ---------------- scratch (static device globals; no allocation) ----------------
__device__ float g_xl [(size_t)Nn * HC];
__device__ float g_xr [(size_t)Nn * HC];
__device__ float g_h  [(size_t)Nn * HC];
__device__ float g_tmp[(size_t)Nn * HC];
__device__ int   g_deg[Nn];
__device__ int   g_rowptr[Nn + 1];
__device__ int   g_cursor[Nn];
__device__ int   g_csrsrc[ETOT];
__device__ float g_colsum[HC];
__device__ float g_colsum2[HC];
__device__ float g_pooled [Bb * HC];
__device__ float g_pooled2[Bb * HC];
__device__ int   g_is64;

// ---------------- index dtype handling ----------------
__global__ void k_detect(const void* ei) {
    const long long* p = (const long long*)ei;
    int ok = 1;
    for (int i = 0; i < 64; i++) {
        long long v = p[i];
        if (v < 0 || v >= (long long)Nn) ok = 0;
    }
    g_is64 = ok;
}

__device__ __forceinline__ int loadIdx(const void* p, long long i) {
    if (g_is64) return (int)((const long long*)p)[i];
    return ((const int*)p)[i];
}

// ---------------- CSR build ----------------
__global__ void k_zero_deg() {
    int i = blockIdx.x * blockDim.x + threadIdx.x;
    if (i < Nn) g_deg[i] = 0;
}

__global__ void k_count(const void* ei) {
    int i = blockIdx.x * blockDim.x + threadIdx.x;
    if (i >= ETOT) return;
    int dst;
    if (i < Ee) dst = loadIdx(ei, (long long)Ee + i);
    else        dst = i - Ee;
    atomicAdd(&g_deg[dst], 1);
}

__global__ void k_scan() {
    __shared__ int ss[1024];
    const int CH = 20;                      // 1024*20 = 20480 >= Nn
    int t = threadIdx.x;
    int base = t * CH;
    int dl[CH];
    int local = 0;
#pragma unroll
    for (int i = 0; i < CH; i++) {
        int idx = base + i;
        int d = (idx < Nn) ? g_deg[idx] : 0;
        dl[i] = d;
        local += d;
    }
    ss[t] = local;
    __syncthreads();
    for (int off = 1; off < 1024; off <<= 1) {
        int v = (t >= off) ? ss[t - off] : 0;
        __syncthreads();
        ss[t] += v;
        __syncthreads();
    }
    int run = (t == 0) ? 0 : ss[t - 1];
#pragma unroll
    for (int i = 0; i < CH; i++) {
        int idx = base + i;
        if (idx < Nn) {
            g_rowptr[idx] = run;
            g_cursor[idx] = run;
            run += dl[i];
        }
    }
    if (t == 1023) g_rowptr[Nn] = ss[1023];
}

__global__ void k_scatter(const void* ei) {
    int i = blockIdx.x * blockDim.x + threadIdx.x;
    if (i >= ETOT) return;
    int src, dst;
    if (i < Ee) {
        src = loadIdx(ei, i);
        dst = loadIdx(ei, (long long)Ee + i);
    } else {
        src = dst = i - Ee;
    }
    int pos = atomicAdd(&g_cursor[dst], 1);
    g_csrsrc[pos] = src;
}

// ---------------- SGEMM: out[M,256] = A[M,256] @ W[256,256] + bias ----------------
// 128x128 block tile, BK=16, 256 threads, 8x8 per thread.
__global__ void k_gemm(const float* __restrict__ Aext,
                       const float* __restrict__ W,
                       const float* __restrict__ bias,
                       int osel) {
    __shared__ float As[16][132];
    __shared__ float Bs[16][128];

    const float* A = Aext ? Aext : g_h;
    float* out = osel ? g_xr : g_xl;
    const int M = Nn;

    int t  = threadIdx.x;
    int bm = blockIdx.x * 128;
    int bn = blockIdx.y * 128;
    int tx = t & 15;
    int ty = t >> 4;

    int la_m = t >> 1;           // 0..127
    int la_k = (t & 1) * 8;      // 0 or 8
    int lb_k = t >> 4;           // 0..15
    int lb_n = (t & 15) * 8;     // 0..120

    float acc[8][8];
#pragma unroll
    for (int i = 0; i < 8; i++)
#pragma unroll
        for (int j = 0; j < 8; j++) acc[i][j] = 0.f;

    for (int k0 = 0; k0 < 256; k0 += 16) {
        float4 a0, a1;
        int row = bm + la_m;
        if (row < M) {
            const float4* ap = (const float4*)(A + (size_t)row * 256 + k0 + la_k);
            a0 = ap[0];
            a1 = ap[1];
        } else {
            a0 = make_float4(0, 0, 0, 0);
            a1 = make_float4(0, 0, 0, 0);
        }
        const float4* bp = (const float4*)(W + (size_t)(k0 + lb_k) * 256 + bn + lb_n);
        float4 b0 = bp[0];
        float4 b1 = bp[1];

        __syncthreads();
        As[la_k + 0][la_m] = a0.x;
        As[la_k + 1][la_m] = a0.y;
        As[la_k + 2][la_m] = a0.z;
        As[la_k + 3][la_m] = a0.w;
        As[la_k + 4][la_m] = a1.x;
        As[la_k + 5][la_m] = a1.y;
        As[la_k + 6][la_m] = a1.z;
        As[la_k + 7][la_m] = a1.w;
        *(float4*)&Bs[lb_k][lb_n]     = b0;
        *(float4*)&Bs[lb_k][lb_n + 4] = b1;
        __syncthreads();

#pragma unroll
        for (int k = 0; k < 16; k++) {
            float4 av0 = *(float4*)&As[k][ty * 8];
            float4 av1 = *(float4*)&As[k][ty * 8 + 4];
            float4 bv0 = *(float4*)&Bs[k][tx * 8];
            float4 bv1 = *(float4*)&Bs[k][tx * 8 + 4];
            float av[8] = {av0.x, av0.y, av0.z, av0.w, av1.x, av1.y, av1.z, av1.w};
            float bv[8] = {bv0.x, bv0.y, bv0.z, bv0.w, bv1.x, bv1.y, bv1.z, bv1.w};
#pragma unroll
            for (int i = 0; i < 8; i++)
#pragma unroll
                for (int j = 0; j < 8; j++) acc[i][j] += av[i] * bv[j];
        }
    }

    float4 bb0 = *(const float4*)(bias + bn + tx * 8);
    float4 bb1 = *(const float4*)(bias + bn + tx * 8 + 4);
    float bbv[8] = {bb0.x, bb0.y, bb0.z, bb0.w, bb1.x, bb1.y, bb1.z, bb1.w};

#pragma unroll
    for (int i = 0; i < 8; i++) {
        int row = bm + ty * 8 + i;
        if (row < M) {
            float4 o0, o1;
            o0.x = acc[i][0] + bbv[0];
            o0.y = acc[i][1] + bbv[1];
            o0.z = acc[i][2] + bbv[2];
            o0.w = acc[i][3] + bbv[3];
            o1.x = acc[i][4] + bbv[4];
            o1.y = acc[i][5] + bbv[5];
            o1.z = acc[i][6] + bbv[6];
            o1.w = acc[i][7] + bbv[7];
            float* op = out + (size_t)row * 256 + bn + tx * 8;
            *(float4*)op       = o0;
            *(float4*)(op + 4) = o1;
        }
    }
}

// ---------------- per-node GATv2 attention (warp/node, online softmax) ----------------
__global__ void k_node(const float* __restrict__ att,
                       const float* __restrict__ cbias) {
    int warp = (blockIdx.x * blockDim.x + threadIdx.x) >> 5;
    int lane = threadIdx.x & 31;
    if (warp >= Nn) return;
    int node  = warp;
    int cbase = lane * 8;     // lane's 8 channels; head = lane>>3

    float4 r0 = *(const float4*)(g_xr + (size_t)node * HC + cbase);
    float4 r1 = *(const float4*)(g_xr + (size_t)node * HC + cbase + 4);
    float rr[8] = {r0.x, r0.y, r0.z, r0.w, r1.x, r1.y, r1.z, r1.w};
    float4 a0 = *(const float4*)(att + cbase);
    float4 a1 = *(const float4*)(att + cbase + 4);
    float aa[8] = {a0.x, a0.y, a0.z, a0.w, a1.x, a1.y, a1.z, a1.w};

    int beg = g_rowptr[node];
    int end = g_rowptr[node + 1];

    float m = -1e30f;
    float denom = 0.f;
    float acc[8] = {0, 0, 0, 0, 0, 0, 0, 0};

    for (int s = beg; s < end; s++) {
        int src = g_csrsrc[s];
        const float4* lp = (const float4*)(g_xl + (size_t)src * HC + cbase);
        float4 l0 = lp[0];
        float4 l1 = lp[1];
        float xs[8] = {l0.x, l0.y, l0.z, l0.w, l1.x, l1.y, l1.z, l1.w};

        float partial = 0.f;
#pragma unroll
        for (int j = 0; j < 8; j++) {
            float v = xs[j] + rr[j];
            v = fmaxf(v, 0.2f * v);      // leaky_relu(0.2)
            partial += v * aa[j];
        }
        partial += __shfl_xor_sync(0xffffffffu, partial, 1);
        partial += __shfl_xor_sync(0xffffffffu, partial, 2);
        partial += __shfl_xor_sync(0xffffffffu, partial, 4);
        float e = partial;               // per-head e, same across 8-lane group

        float mnew  = fmaxf(m, e);
        float scale = __expf(m - mnew);
        float ex    = __expf(e - mnew);
        denom = denom * scale + ex;
#pragma unroll
        for (int j = 0; j < 8; j++) acc[j] = acc[j] * scale + ex * xs[j];
        m = mnew;
    }

    float inv = 1.f / denom;
    float4 o0, o1;
    float4 cb0 = *(const float4*)(cbias + cbase);
    float4 cb1 = *(const float4*)(cbias + cbase + 4);
    o0.x = acc[0] * inv + cb0.x;
    o0.y = acc[1] * inv + cb0.y;
    o0.z = acc[2] * inv + cb0.z;
    o0.w = acc[3] * inv + cb0.w;
    o1.x = acc[4] * inv + cb1.x;
    o1.y = acc[5] * inv + cb1.y;
    o1.z = acc[6] * inv + cb1.z;
    o1.w = acc[7] * inv + cb1.w;
    float* op = g_tmp + (size_t)node * HC + cbase;
    *(float4*)op       = o0;
    *(float4*)(op + 4) = o1;
}

// ---------------- GraphNorm ----------------
__global__ void k_zero_stats() {
    int c = threadIdx.x;
    g_colsum[c]  = 0.f;
    g_colsum2[c] = 0.f;
}

__global__ void k_colsum() {
    int c = threadIdx.x;
    float s = 0.f, s2 = 0.f;
    for (int r = blockIdx.x; r < Nn; r += gridDim.x) {
        float v = g_tmp[(size_t)r * HC + c];
        s  += v;
        s2 += v * v;
    }
    atomicAdd(&g_colsum[c], s);
    atomicAdd(&g_colsum2[c], s2);
}

__global__ void k_apply(const float* __restrict__ w, const float* __restrict__ b,
                        const float* __restrict__ al, const float* __restrict__ pa, int l) {
    int idx = blockIdx.x * blockDim.x + threadIdx.x;
    if (idx >= Nn * HC) return;
    int c = idx & 255;
    float a   = al[c];
    float mu  = g_colsum[c]  * (1.f / Nn);
    float var = g_colsum2[c] * (1.f / Nn) - mu * mu * a * (2.f - a);
    float inv = rsqrtf(var + EPSn);
    float v = g_tmp[idx] - a * mu;
    float y = w[c] * v * inv + b[c];
    g_h[idx] = (y >= 0.f) ? y : pa[l] * y;
}

// ---------------- pooling + final norm + FC ----------------
__global__ void k_zero_pooled() {
    int i = blockIdx.x * blockDim.x + threadIdx.x;
    if (i < Bb * HC) g_pooled[i] = 0.f;
}

__global__ void k_pool(const void* batch) {
    __shared__ int sb[256];
    int r0 = blockIdx.x * 256;
    int t = threadIdx.x;
    int r = r0 + t;
    sb[t] = (r < Nn) ? loadIdx(batch, r) : -1;
    __syncthreads();
    int c = t;
    float s = 0.f;
    int prev = -1;
    int lim = min(256, Nn - r0);
    for (int i = 0; i < lim; i++) {
        int bt = sb[i];
        float v = g_h[(size_t)(r0 + i) * HC + c];
        if (bt != prev) {
            if (prev >= 0) atomicAdd(&g_pooled[prev * HC + c], s);
            s = 0.f;
            prev = bt;
        }
        s += v;
    }
    if (prev >= 0) atomicAdd(&g_pooled[prev * HC + c], s);
}

__global__ void k_pooled_norm(const float* __restrict__ w, const float* __restrict__ b,
                              const float* __restrict__ al) {
    int c = threadIdx.x;
    float s = 0.f, s2 = 0.f;
    for (int r = 0; r < Bb; r++) {
        float v = g_pooled[r * HC + c];
        s  += v;
        s2 += v * v;
    }
    float a   = al[c];
    float mu  = s * (1.f / Bb);
    float var = s2 * (1.f / Bb) - mu * mu * a * (2.f - a);
    float inv = rsqrtf(var + EPSn);
    for (int r = 0; r < Bb; r++) {
        float v = g_pooled[r * HC + c] - a * mu;
        g_pooled2[r * HC + c] = w[c] * v * inv + b[c];
    }
}

__global__ void k_fc(const float* __restrict__ W, const float* __restrict__ bias,
                     float* __restrict__ out) {
    __shared__ float row[HC];
    int bi = blockIdx.x;
    int t  = threadIdx.x;  // 128
    row[t]       = g_pooled2[bi * HC + t];
    row[t + 128] = g_pooled2[bi * HC + t + 128];
    __syncthreads();
    float acc = bias[t];
    for (int k = 0; k < HC; k++) acc += row[k] * W[k * 128 + t];
    out[bi * 128 + t] = acc;
}

// ---------------- launch ----------------
extern "C" void kernel_launch(void* const* d_in, const int* in_sizes, int n_in,
                              void* d_out, int out_size) {
    const float* x   = (const float*)d_in[0];
    const void*  ei  = d_in[1];
    const void*  bat = d_in[2];
    const float* Wl  = (const float*)d_in[3];
    const float* bl  = (const float*)d_in[4];
    const float* Wr  = (const float*)d_in[5];
    const float* br  = (const float*)d_in[6];
    const float* att = (const float*)d_in[7];
    const float* cb  = (const float*)d_in[8];
    const float* pa  = (const float*)d_in[9];
    const float* nw  = (const float*)d_in[10];
    const float* nb  = (const float*)d_in[11];
    const float* na  = (const float*)d_in[12];
    const float* fcW = (const float*)d_in[13];
    const float* fcb = (const float*)d_in[14];
    float* out = (float*)d_out;

    k_detect<<<1, 1>>>(ei);
    k_zero_deg<<<(Nn + 255) / 256, 256>>>();
    k_count<<<(ETOT + 255) / 256, 256>>>(ei);
    k_scan<<<1, 1024>>>();
    k_scatter<<<(ETOT + 255) / 256, 256>>>(ei);

    for (int l = 0; l < 3; l++) {
        const float* Ain = (l == 0) ? x : nullptr;
        k_gemm<<<dim3(157, 2), 256>>>(Ain, Wl + (size_t)l * HC * HC, bl + l * HC, 0);
        k_gemm<<<dim3(157, 2), 256>>>(Ain, Wr + (size_t)l * HC * HC, br + l * HC, 1);
        k_node<<<(Nn * 32 + 255) / 256, 256>>>(att + l * HC, cb + l * HC);
        k_zero_stats<<<1, 256>>>();
        k_colsum<<<256, 256>>>();
        k_apply<<<(Nn * HC + 255) / 256, 256>>>(nw, nb, na, pa, l);
    }

    k_zero_pooled<<<(Bb * HC + 255) / 256, 256>>>();
    k_pool<<<(Nn + 255) / 256, 256>>>(bat);
    k_pooled_norm<<<1, HC>>>(nw, nb, na);
    k_fc<<<Bb, 128>>>(fcW, fcb, out);
}

// round 2
// speedup vs baseline: 1.4015x; 1.4015x over previous
#include <cuda_runtime.h>
#include <cstdint>

#define Nn   20000
#define Ee   640000
#define ETOT (Ee + Nn)
#define Bb   16
#define HC   256
#define EPSn 1e-5f

// ---------------- scratch (static device globals; no allocation) ----------------
__device__ float g_xl [(size_t)Nn * HC];
__device__ float g_xr [(size_t)Nn * HC];
__device__ float g_h  [(size_t)Nn * HC];
__device__ float g_tmp[(size_t)Nn * HC];
__device__ int   g_deg[Nn];
__device__ int   g_rowptr[Nn + 1];
__device__ int   g_cursor[Nn];
__device__ int   g_csrsrc[ETOT];
__device__ float g_colsum[HC];
__device__ float g_colsum2[HC];
__device__ float g_pooled [Bb * HC];
__device__ float g_pooled2[Bb * HC];
__device__ int   g_is64;

// ---------------- index dtype handling ----------------
__global__ void k_detect(const void* ei) {
    const long long* p = (const long long*)ei;
    int ok = 1;
    for (int i = 0; i < 64; i++) {
        long long v = p[i];
        if (v < 0 || v >= (long long)Nn) ok = 0;
    }
    g_is64 = ok;
}

__device__ __forceinline__ int loadIdx(const void* p, long long i) {
    if (g_is64) return (int)((const long long*)p)[i];
    return ((const int*)p)[i];
}

// ---------------- CSR build ----------------
__global__ void k_zero_deg() {
    int i = blockIdx.x * blockDim.x + threadIdx.x;
    if (i < Nn) g_deg[i] = 0;
}

__global__ void k_count(const void* ei) {
    int i = blockIdx.x * blockDim.x + threadIdx.x;
    if (i >= ETOT) return;
    int dst;
    if (i < Ee) dst = loadIdx(ei, (long long)Ee + i);
    else        dst = i - Ee;
    atomicAdd(&g_deg[dst], 1);
}

__global__ void k_scan() {
    __shared__ int ss[1024];
    const int CH = 20;
    int t = threadIdx.x;
    int base = t * CH;
    int dl[CH];
    int local = 0;
#pragma unroll
    for (int i = 0; i < CH; i++) {
        int idx = base + i;
        int d = (idx < Nn) ? g_deg[idx] : 0;
        dl[i] = d;
        local += d;
    }
    ss[t] = local;
    __syncthreads();
    for (int off = 1; off < 1024; off <<= 1) {
        int v = (t >= off) ? ss[t - off] : 0;
        __syncthreads();
        ss[t] += v;
        __syncthreads();
    }
    int run = (t == 0) ? 0 : ss[t - 1];
#pragma unroll
    for (int i = 0; i < CH; i++) {
        int idx = base + i;
        if (idx < Nn) {
            g_rowptr[idx] = run;
            g_cursor[idx] = run;
            run += dl[i];
        }
    }
    if (t == 1023) g_rowptr[Nn] = ss[1023];
}

__global__ void k_scatter(const void* ei) {
    int i = blockIdx.x * blockDim.x + threadIdx.x;
    if (i >= ETOT) return;
    int src, dst;
    if (i < Ee) {
        src = loadIdx(ei, i);
        dst = loadIdx(ei, (long long)Ee + i);
    } else {
        src = dst = i - Ee;
    }
    int pos = atomicAdd(&g_cursor[dst], 1);
    g_csrsrc[pos] = src;
}

// ---------------- tf32 split helper ----------------
__device__ __forceinline__ void tf32split(float v, uint32_t& hi, uint32_t& lo) {
    asm("cvt.rna.tf32.f32 %0, %1;" : "=r"(hi) : "f"(v));
    float l = v - __uint_as_float(hi);
    asm("cvt.rna.tf32.f32 %0, %1;" : "=r"(lo) : "f"(l));
}

__device__ __forceinline__ void mma_tf32(float* c, uint32_t a0, uint32_t a1,
                                         uint32_t a2, uint32_t a3,
                                         uint32_t b0, uint32_t b1) {
    asm volatile(
        "mma.sync.aligned.m16n8k8.row.col.f32.tf32.tf32.f32 "
        "{%0,%1,%2,%3}, {%4,%5,%6,%7}, {%8,%9}, {%0,%1,%2,%3};"
        : "+f"(c[0]), "+f"(c[1]), "+f"(c[2]), "+f"(c[3])
        : "r"(a0), "r"(a1), "r"(a2), "r"(a3), "r"(b0), "r"(b1));
}

// ---------------- tensor-core GEMM (3xTF32), fused Wl+Wr ----------------
// out[M,256] = A[M,256] @ W[256,256] + bias.
// Grid: (157, 4). y: bit0 -> n half (0..127 / 128..255), bit1 -> weight (Wl/Wr).
// CTA: 128(M) x 128(N), 8 warps in 4(M) x 2(N), warp tile 32x64, k-step 16.
__global__ void __launch_bounds__(256)
k_gemm_mma(const float* __restrict__ Aext,
           const float* __restrict__ Wl_, const float* __restrict__ bl_,
           const float* __restrict__ Wr_, const float* __restrict__ br_) {
    __shared__ float Ah[128][20];
    __shared__ float Al[128][20];
    __shared__ float Bh[16][136];
    __shared__ float Bl[16][136];

    const float* A = Aext ? Aext : g_h;
    int y    = blockIdx.y;
    int wsel = y >> 1;
    int bn   = (y & 1) * 128;
    const float* W    = wsel ? Wr_ : Wl_;
    const float* bias = wsel ? br_ : bl_;
    float* out        = wsel ? g_xr : g_xl;

    int bm   = blockIdx.x * 128;
    int t    = threadIdx.x;
    int lane = t & 31;
    int w    = t >> 5;
    int wm   = (w & 3) * 32;     // warp M offset
    int wn   = (w >> 2) * 64;    // warp N offset
    int grp  = lane >> 2;        // 0..7
    int tig  = lane & 3;         // 0..3

    float acc[2][8][4];
#pragma unroll
    for (int mi = 0; mi < 2; mi++)
#pragma unroll
        for (int ni = 0; ni < 8; ni++)
#pragma unroll
            for (int q = 0; q < 4; q++) acc[mi][ni][q] = 0.f;

    for (int k0 = 0; k0 < 256; k0 += 16) {
        // global loads: 2 A float4 + 2 B float4 per thread
        float4 av[2], bv[2];
#pragma unroll
        for (int j = 0; j < 2; j++) {
            int i = t + 256 * j;
            int row = i >> 2;          // 0..127
            int cg  = i & 3;           // 0..3
            int grow = bm + row;
            if (grow < Nn)
                av[j] = *(const float4*)(A + (size_t)grow * 256 + k0 + cg * 4);
            else
                av[j] = make_float4(0, 0, 0, 0);
            int br_ = i >> 5;          // 0..15
            int bc  = i & 31;          // 0..31
            bv[j] = *(const float4*)(W + (size_t)(k0 + br_) * 256 + bn + bc * 4);
        }
        __syncthreads();
#pragma unroll
        for (int j = 0; j < 2; j++) {
            int i = t + 256 * j;
            int row = i >> 2, cg = i & 3;
            uint32_t h0, l0, h1, l1, h2, l2, h3, l3;
            tf32split(av[j].x, h0, l0);
            tf32split(av[j].y, h1, l1);
            tf32split(av[j].z, h2, l2);
            tf32split(av[j].w, h3, l3);
            Ah[row][cg * 4 + 0] = __uint_as_float(h0);
            Ah[row][cg * 4 + 1] = __uint_as_float(h1);
            Ah[row][cg * 4 + 2] = __uint_as_float(h2);
            Ah[row][cg * 4 + 3] = __uint_as_float(h3);
            Al[row][cg * 4 + 0] = __uint_as_float(l0);
            Al[row][cg * 4 + 1] = __uint_as_float(l1);
            Al[row][cg * 4 + 2] = __uint_as_float(l2);
            Al[row][cg * 4 + 3] = __uint_as_float(l3);
            int br_ = i >> 5, bc = i & 31;
            tf32split(bv[j].x, h0, l0);
            tf32split(bv[j].y, h1, l1);
            tf32split(bv[j].z, h2, l2);
            tf32split(bv[j].w, h3, l3);
            Bh[br_][bc * 4 + 0] = __uint_as_float(h0);
            Bh[br_][bc * 4 + 1] = __uint_as_float(h1);
            Bh[br_][bc * 4 + 2] = __uint_as_float(h2);
            Bh[br_][bc * 4 + 3] = __uint_as_float(h3);
            Bl[br_][bc * 4 + 0] = __uint_as_float(l0);
            Bl[br_][bc * 4 + 1] = __uint_as_float(l1);
            Bl[br_][bc * 4 + 2] = __uint_as_float(l2);
            Bl[br_][bc * 4 + 3] = __uint_as_float(l3);
        }
        __syncthreads();

#pragma unroll
        for (int ks = 0; ks < 16; ks += 8) {
            // B fragments for this k-sub: 8 ntiles x {b0,b1} x {hi,lo}
            uint32_t bh[8][2], blo[8][2];
#pragma unroll
            for (int ni = 0; ni < 8; ni++) {
                int col = wn + ni * 8 + grp;
                bh[ni][0]  = __float_as_uint(Bh[ks + tig][col]);
                bh[ni][1]  = __float_as_uint(Bh[ks + tig + 4][col]);
                blo[ni][0] = __float_as_uint(Bl[ks + tig][col]);
                blo[ni][1] = __float_as_uint(Bl[ks + tig + 4][col]);
            }
#pragma unroll
            for (int mi = 0; mi < 2; mi++) {
                int rb = wm + mi * 16;
                uint32_t ah0 = __float_as_uint(Ah[rb + grp][ks + tig]);
                uint32_t ah1 = __float_as_uint(Ah[rb + grp + 8][ks + tig]);
                uint32_t ah2 = __float_as_uint(Ah[rb + grp][ks + tig + 4]);
                uint32_t ah3 = __float_as_uint(Ah[rb + grp + 8][ks + tig + 4]);
                uint32_t al0 = __float_as_uint(Al[rb + grp][ks + tig]);
                uint32_t al1 = __float_as_uint(Al[rb + grp + 8][ks + tig]);
                uint32_t al2 = __float_as_uint(Al[rb + grp][ks + tig + 4]);
                uint32_t al3 = __float_as_uint(Al[rb + grp + 8][ks + tig + 4]);
#pragma unroll
                for (int ni = 0; ni < 8; ni++) {
                    mma_tf32(acc[mi][ni], ah0, ah1, ah2, ah3, bh[ni][0], bh[ni][1]);
                    mma_tf32(acc[mi][ni], ah0, ah1, ah2, ah3, blo[ni][0], blo[ni][1]);
                    mma_tf32(acc[mi][ni], al0, al1, al2, al3, bh[ni][0], bh[ni][1]);
                }
            }
        }
    }

    // epilogue: add bias, store
#pragma unroll
    for (int mi = 0; mi < 2; mi++) {
#pragma unroll
        for (int ni = 0; ni < 8; ni++) {
            int col = bn + wn + ni * 8 + tig * 2;
            float b0 = bias[col], b1 = bias[col + 1];
            int r0 = bm + wm + mi * 16 + grp;
            int r1 = r0 + 8;
            if (r0 < Nn) {
                float2 v = make_float2(acc[mi][ni][0] + b0, acc[mi][ni][1] + b1);
                *(float2*)(out + (size_t)r0 * 256 + col) = v;
            }
            if (r1 < Nn) {
                float2 v = make_float2(acc[mi][ni][2] + b0, acc[mi][ni][3] + b1);
                *(float2*)(out + (size_t)r1 * 256 + col) = v;
            }
        }
    }
}

// ---------------- per-node GATv2 attention (warp/node, online softmax, 2x unroll) ----------------
__global__ void k_node(const float* __restrict__ att,
                       const float* __restrict__ cbias) {
    int warp = (blockIdx.x * blockDim.x + threadIdx.x) >> 5;
    int lane = threadIdx.x & 31;
    if (warp >= Nn) return;
    int node  = warp;
    int cbase = lane * 8;

    float4 r0 = *(const float4*)(g_xr + (size_t)node * HC + cbase);
    float4 r1 = *(const float4*)(g_xr + (size_t)node * HC + cbase + 4);
    float rr[8] = {r0.x, r0.y, r0.z, r0.w, r1.x, r1.y, r1.z, r1.w};
    float4 a0 = *(const float4*)(att + cbase);
    float4 a1 = *(const float4*)(att + cbase + 4);
    float aa[8] = {a0.x, a0.y, a0.z, a0.w, a1.x, a1.y, a1.z, a1.w};

    int beg = g_rowptr[node];
    int end = g_rowptr[node + 1];

    float m = -1e30f;
    float denom = 0.f;
    float acc[8] = {0, 0, 0, 0, 0, 0, 0, 0};

    int s = beg;
    for (; s + 2 <= end; s += 2) {
        int s0 = g_csrsrc[s];
        int s1 = g_csrsrc[s + 1];
        const float4* lp0 = (const float4*)(g_xl + (size_t)s0 * HC + cbase);
        const float4* lp1 = (const float4*)(g_xl + (size_t)s1 * HC + cbase);
        float4 x00 = lp0[0], x01 = lp0[1];
        float4 x10 = lp1[0], x11 = lp1[1];
        float xs0[8] = {x00.x, x00.y, x00.z, x00.w, x01.x, x01.y, x01.z, x01.w};
        float xs1[8] = {x10.x, x10.y, x10.z, x10.w, x11.x, x11.y, x11.z, x11.w};

        float p0 = 0.f, p1 = 0.f;
#pragma unroll
        for (int j = 0; j < 8; j++) {
            float v0 = xs0[j] + rr[j];
            float v1 = xs1[j] + rr[j];
            v0 = fmaxf(v0, 0.2f * v0);
            v1 = fmaxf(v1, 0.2f * v1);
            p0 += v0 * aa[j];
            p1 += v1 * aa[j];
        }
        p0 += __shfl_xor_sync(0xffffffffu, p0, 1);
        p1 += __shfl_xor_sync(0xffffffffu, p1, 1);
        p0 += __shfl_xor_sync(0xffffffffu, p0, 2);
        p1 += __shfl_xor_sync(0xffffffffu, p1, 2);
        p0 += __shfl_xor_sync(0xffffffffu, p0, 4);
        p1 += __shfl_xor_sync(0xffffffffu, p1, 4);

        float mnew  = fmaxf(m, fmaxf(p0, p1));
        float scale = __expf(m - mnew);
        float ex0   = __expf(p0 - mnew);
        float ex1   = __expf(p1 - mnew);
        denom = denom * scale + ex0 + ex1;
#pragma unroll
        for (int j = 0; j < 8; j++)
            acc[j] = acc[j] * scale + ex0 * xs0[j] + ex1 * xs1[j];
        m = mnew;
    }
    if (s < end) {
        int s0 = g_csrsrc[s];
        const float4* lp = (const float4*)(g_xl + (size_t)s0 * HC + cbase);
        float4 l0 = lp[0], l1 = lp[1];
        float xs[8] = {l0.x, l0.y, l0.z, l0.w, l1.x, l1.y, l1.z, l1.w};
        float p = 0.f;
#pragma unroll
        for (int j = 0; j < 8; j++) {
            float v = xs[j] + rr[j];
            v = fmaxf(v, 0.2f * v);
            p += v * aa[j];
        }
        p += __shfl_xor_sync(0xffffffffu, p, 1);
        p += __shfl_xor_sync(0xffffffffu, p, 2);
        p += __shfl_xor_sync(0xffffffffu, p, 4);
        float mnew  = fmaxf(m, p);
        float scale = __expf(m - mnew);
        float ex    = __expf(p - mnew);
        denom = denom * scale + ex;
#pragma unroll
        for (int j = 0; j < 8; j++) acc[j] = acc[j] * scale + ex * xs[j];
        m = mnew;
    }

    float inv = 1.f / denom;
    float4 cb0 = *(const float4*)(cbias + cbase);
    float4 cb1 = *(const float4*)(cbias + cbase + 4);
    float4 o0, o1;
    o0.x = acc[0] * inv + cb0.x;
    o0.y = acc[1] * inv + cb0.y;
    o0.z = acc[2] * inv + cb0.z;
    o0.w = acc[3] * inv + cb0.w;
    o1.x = acc[4] * inv + cb1.x;
    o1.y = acc[5] * inv + cb1.y;
    o1.z = acc[6] * inv + cb1.z;
    o1.w = acc[7] * inv + cb1.w;
    float* op = g_tmp + (size_t)node * HC + cbase;
    *(float4*)op       = o0;
    *(float4*)(op + 4) = o1;
}

// ---------------- GraphNorm ----------------
__global__ void k_zero_stats() {
    int c = threadIdx.x;
    g_colsum[c]  = 0.f;
    g_colsum2[c] = 0.f;
}

__global__ void k_colsum() {
    int c = threadIdx.x;
    float s = 0.f, s2 = 0.f;
    for (int r = blockIdx.x; r < Nn; r += gridDim.x) {
        float v = g_tmp[(size_t)r * HC + c];
        s  += v;
        s2 += v * v;
    }
    atomicAdd(&g_colsum[c], s);
    atomicAdd(&g_colsum2[c], s2);
}

__global__ void k_apply(const float* __restrict__ w, const float* __restrict__ b,
                        const float* __restrict__ al, const float* __restrict__ pa, int l) {
    int idx = blockIdx.x * blockDim.x + threadIdx.x;   // float4 index
    if (idx >= Nn * HC / 4) return;
    int c4 = (idx & 63) * 4;
    float slope = pa[l];
    float4 av = *(const float4*)(al + c4);
    float4 wv = *(const float4*)(w + c4);
    float4 bv = *(const float4*)(b + c4);
    float4 tv = *(((const float4*)g_tmp) + idx);
    float* aa = &av.x; float* ww = &wv.x; float* bb = &bv.x; float* tt = &tv.x;
    float4 ov;
    float* oo = &ov.x;
#pragma unroll
    for (int j = 0; j < 4; j++) {
        int c = c4 + j;
        float a   = aa[j];
        float mu  = g_colsum[c]  * (1.f / Nn);
        float var = g_colsum2[c] * (1.f / Nn) - mu * mu * a * (2.f - a);
        float inv = rsqrtf(var + EPSn);
        float v = tt[j] - a * mu;
        float yv = ww[j] * v * inv + bb[j];
        oo[j] = (yv >= 0.f) ? yv : slope * yv;
    }
    *(((float4*)g_h) + idx) = ov;
}

// ---------------- pooling + final norm + FC ----------------
__global__ void k_zero_pooled() {
    int i = blockIdx.x * blockDim.x + threadIdx.x;
    if (i < Bb * HC) g_pooled[i] = 0.f;
}

__global__ void k_pool(const void* batch) {
    __shared__ int sb[256];
    int r0 = blockIdx.x * 256;
    int t = threadIdx.x;
    int r = r0 + t;
    sb[t] = (r < Nn) ? loadIdx(batch, r) : -1;
    __syncthreads();
    int c = t;
    float s = 0.f;
    int prev = -1;
    int lim = min(256, Nn - r0);
    for (int i = 0; i < lim; i++) {
        int bt = sb[i];
        float v = g_h[(size_t)(r0 + i) * HC + c];
        if (bt != prev) {
            if (prev >= 0) atomicAdd(&g_pooled[prev * HC + c], s);
            s = 0.f;
            prev = bt;
        }
        s += v;
    }
    if (prev >= 0) atomicAdd(&g_pooled[prev * HC + c], s);
}

__global__ void k_pooled_norm(const float* __restrict__ w, const float* __restrict__ b,
                              const float* __restrict__ al) {
    int c = threadIdx.x;
    float s = 0.f, s2 = 0.f;
    for (int r = 0; r < Bb; r++) {
        float v = g_pooled[r * HC + c];
        s  += v;
        s2 += v * v;
    }
    float a   = al[c];
    float mu  = s * (1.f / Bb);
    float var = s2 * (1.f / Bb) - mu * mu * a * (2.f - a);
    float inv = rsqrtf(var + EPSn);
    for (int r = 0; r < Bb; r++) {
        float v = g_pooled[r * HC + c] - a * mu;
        g_pooled2[r * HC + c] = w[c] * v * inv + b[c];
    }
}

__global__ void k_fc(const float* __restrict__ W, const float* __restrict__ bias,
                     float* __restrict__ out) {
    __shared__ float row[HC];
    int bi = blockIdx.x;
    int t  = threadIdx.x;  // 128
    row[t]       = g_pooled2[bi * HC + t];
    row[t + 128] = g_pooled2[bi * HC + t + 128];
    __syncthreads();
    float acc = bias[t];
    for (int k = 0; k < HC; k++) acc += row[k] * W[k * 128 + t];
    out[bi * 128 + t] = acc;
}

// ---------------- launch ----------------
extern "C" void kernel_launch(void* const* d_in, const int* in_sizes, int n_in,
                              void* d_out, int out_size) {
    const float* x   = (const float*)d_in[0];
    const void*  ei  = d_in[1];
    const void*  bat = d_in[2];
    const float* Wl  = (const float*)d_in[3];
    const float* bl  = (const float*)d_in[4];
    const float* Wr  = (const float*)d_in[5];
    const float* br  = (const float*)d_in[6];
    const float* att = (const float*)d_in[7];
    const float* cb  = (const float*)d_in[8];
    const float* pa  = (const float*)d_in[9];
    const float* nw  = (const float*)d_in[10];
    const float* nb  = (const float*)d_in[11];
    const float* na  = (const float*)d_in[12];
    const float* fcW = (const float*)d_in[13];
    const float* fcb = (const float*)d_in[14];
    float* out = (float*)d_out;

    k_detect<<<1, 1>>>(ei);
    k_zero_deg<<<(Nn + 255) / 256, 256>>>();
    k_count<<<(ETOT + 255) / 256, 256>>>(ei);
    k_scan<<<1, 1024>>>();
    k_scatter<<<(ETOT + 255) / 256, 256>>>(ei);

    for (int l = 0; l < 3; l++) {
        const float* Ain = (l == 0) ? x : nullptr;
        k_gemm_mma<<<dim3(157, 4), 256>>>(Ain,
                                          Wl + (size_t)l * HC * HC, bl + l * HC,
                                          Wr + (size_t)l * HC * HC, br + l * HC);
        k_node<<<(Nn * 32 + 255) / 256, 256>>>(att + l * HC, cb + l * HC);
        k_zero_stats<<<1, 256>>>();
        k_colsum<<<256, 256>>>();
        k_apply<<<(Nn * HC / 4 + 255) / 256, 256>>>(nw, nb, na, pa, l);
    }

    k_zero_pooled<<<(Bb * HC + 255) / 256, 256>>>();
    k_pool<<<(Nn + 255) / 256, 256>>>(bat);
    k_pooled_norm<<<1, HC>>>(nw, nb, na);
    k_fc<<<Bb, 128>>>(fcW, fcb, out);
}